// round 1
// baseline (speedup 1.0000x reference)
#include <cuda_runtime.h>
#include <cuda_bf16.h>
#include <math.h>

// Problem constants
#define BB 2
#define SS 4096
#define DD 512
#define HH 8
#define DH 64
#define TT (BB * SS)   // 8192 tokens

// ---------------- scratch (device globals; no allocations allowed) ----------
__device__ float g_Q[TT * DD];
__device__ float g_K[TT * DD];
__device__ float g_V[TT * DD];
__device__ float g_A[TT * DD];

// ============================================================================
// GEMM: out[m][n] = sum_k X[m][k] * W[n][k] + bias[n]
// X: (M, K) row-major, W: (N, K) row-major (nn.Linear weight), out: (M, N)
// Tiles: 128x128x16, 256 threads, 8x8 microtile (split 4+4 in both dims)
// ============================================================================
__global__ __launch_bounds__(256, 2)
void gemm_xwt_bias(const float* __restrict__ X, const float* __restrict__ W,
                   const float* __restrict__ bias, float* __restrict__ out,
                   int M, int N, int K) {
    __shared__ float Xs[16][128];
    __shared__ float Ws[16][128];

    const int tid  = threadIdx.x;
    const int trow = tid >> 4;    // 0..15
    const int tcol = tid & 15;    // 0..15
    const int m0 = blockIdx.x * 128;
    const int n0 = blockIdx.y * 128;

    const int lr = tid >> 2;          // 0..63 (tile row for loads)
    const int lc = (tid & 3) * 4;     // 0,4,8,12 (k offset for loads)

    float acc[8][8];
#pragma unroll
    for (int i = 0; i < 8; i++)
#pragma unroll
        for (int j = 0; j < 8; j++) acc[i][j] = 0.f;

    for (int kt = 0; kt < K; kt += 16) {
        // load X tile (transposed into Xs[k][m]) and W tile (Ws[k][n])
#pragma unroll
        for (int half = 0; half < 2; half++) {
            int row = lr + half * 64;
            float4 xv = *(const float4*)&X[(size_t)(m0 + row) * K + kt + lc];
            Xs[lc + 0][row] = xv.x;
            Xs[lc + 1][row] = xv.y;
            Xs[lc + 2][row] = xv.z;
            Xs[lc + 3][row] = xv.w;
            float4 wv = *(const float4*)&W[(size_t)(n0 + row) * K + kt + lc];
            Ws[lc + 0][row] = wv.x;
            Ws[lc + 1][row] = wv.y;
            Ws[lc + 2][row] = wv.z;
            Ws[lc + 3][row] = wv.w;
        }
        __syncthreads();

#pragma unroll
        for (int kk = 0; kk < 16; kk++) {
            float a[8], b[8];
            float4 t;
            t = *(const float4*)&Xs[kk][trow * 4];
            a[0] = t.x; a[1] = t.y; a[2] = t.z; a[3] = t.w;
            t = *(const float4*)&Xs[kk][64 + trow * 4];
            a[4] = t.x; a[5] = t.y; a[6] = t.z; a[7] = t.w;
            t = *(const float4*)&Ws[kk][tcol * 4];
            b[0] = t.x; b[1] = t.y; b[2] = t.z; b[3] = t.w;
            t = *(const float4*)&Ws[kk][64 + tcol * 4];
            b[4] = t.x; b[5] = t.y; b[6] = t.z; b[7] = t.w;
#pragma unroll
            for (int i = 0; i < 8; i++)
#pragma unroll
                for (int j = 0; j < 8; j++) acc[i][j] += a[i] * b[j];
        }
        __syncthreads();
    }

    // epilogue: add bias, write out
#pragma unroll
    for (int i = 0; i < 8; i++) {
        int m = m0 + ((i < 4) ? (trow * 4 + i) : (64 + trow * 4 + i - 4));
#pragma unroll
        for (int jh = 0; jh < 2; jh++) {
            int n = n0 + jh * 64 + tcol * 4;
            float4 bv = *(const float4*)&bias[n];
            float4 r;
            r.x = acc[i][jh * 4 + 0] + bv.x;
            r.y = acc[i][jh * 4 + 1] + bv.y;
            r.z = acc[i][jh * 4 + 2] + bv.z;
            r.w = acc[i][jh * 4 + 3] + bv.w;
            *(float4*)&out[(size_t)m * N + n] = r;
        }
    }
}

// ============================================================================
// Flash attention (fp32, online softmax, full attention, no mask)
// Grid: (S/128, H, B); 256 threads.
// Block handles 128 query rows of one (b,h); loops over 4096 keys in 64-chunks.
// SMEM: Qs[64][128] (d-major, pre-scaled), Ks[64][64] (d-major),
//       Vs[64][64] (j-major), Ps[128][68] (padded stride 68).
// ============================================================================
#define ATTN_SMEM_FLOATS (64 * 128 + 64 * 64 + 64 * 64 + 128 * 68)
#define ATTN_SMEM_BYTES (ATTN_SMEM_FLOATS * 4)

__global__ __launch_bounds__(256, 2)
void attn_kernel(const float* __restrict__ Qg, const float* __restrict__ Kg,
                 const float* __restrict__ Vg, float* __restrict__ Og) {
    extern __shared__ float smem[];
    float* Qs = smem;               // [64][128]
    float* Ks = Qs + 64 * 128;      // [64][64]
    float* Vs = Ks + 64 * 64;       // [64][64]
    float* Ps = Vs + 64 * 64;       // [128][68]

    const int b  = blockIdx.z;
    const int h  = blockIdx.y;
    const int q0 = blockIdx.x * 128;
    const int tid  = threadIdx.x;
    const int trow = tid >> 4;   // 0..15
    const int tcol = tid & 15;   // 0..15
    const float scale = 0.125f;  // 1/sqrt(64)

    // load Q tile transposed into Qs[d][r], pre-scaled
    {
        int r  = tid >> 1;
        int d0 = (tid & 1) * 32;
        const float* src = Qg + ((size_t)(b * SS + q0 + r)) * DD + h * DH + d0;
#pragma unroll
        for (int dd = 0; dd < 32; dd += 4) {
            float4 v = *(const float4*)(src + dd);
            Qs[(d0 + dd + 0) * 128 + r] = v.x * scale;
            Qs[(d0 + dd + 1) * 128 + r] = v.y * scale;
            Qs[(d0 + dd + 2) * 128 + r] = v.z * scale;
            Qs[(d0 + dd + 3) * 128 + r] = v.w * scale;
        }
    }

    float o[8][4];
    float mrow[8], lrow[8];
#pragma unroll
    for (int i = 0; i < 8; i++) {
        mrow[i] = -1e30f;
        lrow[i] = 0.f;
#pragma unroll
        for (int c = 0; c < 4; c++) o[i][c] = 0.f;
    }

    const int jload = tid >> 2;          // 0..63
    const int dload = (tid & 3) * 16;    // 0,16,32,48
    const float* kbase = Kg + ((size_t)(b * SS + jload)) * DD + h * DH + dload;
    const float* vbase = Vg + ((size_t)(b * SS + jload)) * DD + h * DH + dload;

    for (int kt = 0; kt < SS; kt += 64) {
        __syncthreads();  // protect Ks/Vs (prev iter readers) + Qs on iter 0

        // load K tile transposed (Ks[d][j]) and V tile straight (Vs[j][d])
#pragma unroll
        for (int dd = 0; dd < 16; dd += 4) {
            float4 kv = *(const float4*)(kbase + (size_t)kt * DD + dd);
            Ks[(dload + dd + 0) * 64 + jload] = kv.x;
            Ks[(dload + dd + 1) * 64 + jload] = kv.y;
            Ks[(dload + dd + 2) * 64 + jload] = kv.z;
            Ks[(dload + dd + 3) * 64 + jload] = kv.w;
            float4 vv = *(const float4*)(vbase + (size_t)kt * DD + dd);
            *(float4*)&Vs[jload * 64 + dload + dd] = vv;
        }
        __syncthreads();

        // ---- S = (Q*scale) @ K^T : per-thread 8x4 microtile ----
        float s[8][4];
#pragma unroll
        for (int i = 0; i < 8; i++)
#pragma unroll
            for (int j = 0; j < 4; j++) s[i][j] = 0.f;

#pragma unroll 8
        for (int d = 0; d < DH; d++) {
            float a[8], kk[4];
            float4 t;
            t = *(const float4*)&Qs[d * 128 + trow * 4];
            a[0] = t.x; a[1] = t.y; a[2] = t.z; a[3] = t.w;
            t = *(const float4*)&Qs[d * 128 + 64 + trow * 4];
            a[4] = t.x; a[5] = t.y; a[6] = t.z; a[7] = t.w;
            t = *(const float4*)&Ks[d * 64 + tcol * 4];
            kk[0] = t.x; kk[1] = t.y; kk[2] = t.z; kk[3] = t.w;
#pragma unroll
            for (int i = 0; i < 8; i++)
#pragma unroll
                for (int j = 0; j < 4; j++) s[i][j] += a[i] * kk[j];
        }

        // ---- online softmax + stage P to shared ----
#pragma unroll
        for (int i = 0; i < 8; i++) {
            float mx = fmaxf(fmaxf(s[i][0], s[i][1]), fmaxf(s[i][2], s[i][3]));
#pragma unroll
            for (int off = 8; off >= 1; off >>= 1)
                mx = fmaxf(mx, __shfl_xor_sync(0xffffffffu, mx, off));
            float mnew  = fmaxf(mrow[i], mx);
            float alpha = __expf(mrow[i] - mnew);
            float psum  = 0.f;
#pragma unroll
            for (int j = 0; j < 4; j++) {
                float p = __expf(s[i][j] - mnew);
                s[i][j] = p;
                psum += p;
            }
#pragma unroll
            for (int off = 8; off >= 1; off >>= 1)
                psum += __shfl_xor_sync(0xffffffffu, psum, off);
            lrow[i] = lrow[i] * alpha + psum;
            mrow[i] = mnew;
#pragma unroll
            for (int c = 0; c < 4; c++) o[i][c] *= alpha;
            int r = (i < 4) ? (trow * 4 + i) : (64 + trow * 4 + i - 4);
            *(float4*)&Ps[r * 68 + tcol * 4] =
                make_float4(s[i][0], s[i][1], s[i][2], s[i][3]);
        }
        __syncthreads();

        // ---- O += P @ V : per-thread 8 rows x 4 d-cols ----
        const float* p0 = &Ps[(trow * 4) * 68];
        const float* p1 = &Ps[(64 + trow * 4) * 68];
#pragma unroll 8
        for (int j = 0; j < 64; j++) {
            float4 vv = *(const float4*)&Vs[j * 64 + tcol * 4];
            float pr[8];
#pragma unroll
            for (int i = 0; i < 4; i++) pr[i]     = p0[i * 68 + j];
#pragma unroll
            for (int i = 0; i < 4; i++) pr[4 + i] = p1[i * 68 + j];
#pragma unroll
            for (int i = 0; i < 8; i++) {
                o[i][0] += pr[i] * vv.x;
                o[i][1] += pr[i] * vv.y;
                o[i][2] += pr[i] * vv.z;
                o[i][3] += pr[i] * vv.w;
            }
        }
    }

    // epilogue: normalize and write merged-head layout (token, h*64+d)
#pragma unroll
    for (int i = 0; i < 8; i++) {
        float inv = 1.f / lrow[i];
        int r = (i < 4) ? (trow * 4 + i) : (64 + trow * 4 + i - 4);
        float* dst = Og + ((size_t)(b * SS + q0 + r)) * DD + h * DH + tcol * 4;
        *(float4*)dst = make_float4(o[i][0] * inv, o[i][1] * inv,
                                    o[i][2] * inv, o[i][3] * inv);
    }
}

// ============================================================================
// kernel_launch
// ============================================================================
extern "C" void kernel_launch(void* const* d_in, const int* in_sizes, int n_in,
                              void* d_out, int out_size) {
    const float* q  = (const float*)d_in[0];
    const float* Wq = (const float*)d_in[1];
    const float* bq = (const float*)d_in[2];
    const float* Wk = (const float*)d_in[3];
    const float* bk = (const float*)d_in[4];
    const float* Wv = (const float*)d_in[5];
    const float* bv = (const float*)d_in[6];
    const float* Wo = (const float*)d_in[7];
    const float* bo = (const float*)d_in[8];
    float* out = (float*)d_out;

    float *gq, *gk, *gv, *ga;
    cudaGetSymbolAddress((void**)&gq, g_Q);
    cudaGetSymbolAddress((void**)&gk, g_K);
    cudaGetSymbolAddress((void**)&gv, g_V);
    cudaGetSymbolAddress((void**)&ga, g_A);

    cudaFuncSetAttribute(attn_kernel, cudaFuncAttributeMaxDynamicSharedMemorySize,
                         ATTN_SMEM_BYTES);

    dim3 gemm_grid(TT / 128, DD / 128);  // (64, 4)
    dim3 gemm_block(256);

    // Q/K/V projections
    gemm_xwt_bias<<<gemm_grid, gemm_block>>>(q, Wq, bq, gq, TT, DD, DD);
    gemm_xwt_bias<<<gemm_grid, gemm_block>>>(q, Wk, bk, gk, TT, DD, DD);
    gemm_xwt_bias<<<gemm_grid, gemm_block>>>(q, Wv, bv, gv, TT, DD, DD);

    // attention
    dim3 attn_grid(SS / 128, HH, BB);    // (32, 8, 2)
    attn_kernel<<<attn_grid, 256, ATTN_SMEM_BYTES>>>(gq, gk, gv, ga);

    // output projection
    gemm_xwt_bias<<<gemm_grid, gemm_block>>>(ga, Wo, bo, out, TT, DD, DD);
}

// round 2
// speedup vs baseline: 2.3211x; 2.3211x over previous
#include <cuda_runtime.h>
#include <cuda_bf16.h>
#include <math.h>

// Problem constants
#define BB 2
#define SS 4096
#define DD 512
#define HH 8
#define DH 64
#define TT (BB * SS)   // 8192 tokens

// ---------------- scratch (device globals; no allocations allowed) ----------
__device__ float g_Q[TT * DD];
__device__ float g_K[TT * DD];
__device__ float g_V[TT * DD];
__device__ float g_A[TT * DD];

// ---------------------------------------------------------------------------
// tf32 helpers (legacy warp-level tensor core path, m16n8k8)
// ---------------------------------------------------------------------------
__device__ __forceinline__ unsigned f2tf(float f) {
    unsigned u;
    asm("cvt.rna.tf32.f32 %0, %1;" : "=r"(u) : "f"(f));
    return u;
}
__device__ __forceinline__ float f2tf_f(float f) {
    return __uint_as_float(f2tf(f));
}
__device__ __forceinline__ void mma_tf32(float c[4],
                                         unsigned a0, unsigned a1,
                                         unsigned a2, unsigned a3,
                                         unsigned b0, unsigned b1) {
    asm volatile(
        "mma.sync.aligned.m16n8k8.row.col.f32.tf32.tf32.f32 "
        "{%0,%1,%2,%3}, {%4,%5,%6,%7}, {%8,%9}, {%0,%1,%2,%3};"
        : "+f"(c[0]), "+f"(c[1]), "+f"(c[2]), "+f"(c[3])
        : "r"(a0), "r"(a1), "r"(a2), "r"(a3), "r"(b0), "r"(b1));
}

// ============================================================================
// GEMM: out[m][n] = sum_k X[m][k] * W[n][k] + bias[n]   (tf32 tensor cores)
// Block 128x128, BK=16, 256 threads = 8 warps (2x4), warp tile 64x32.
// ============================================================================
__global__ __launch_bounds__(256, 2)
void gemm_mma(const float* __restrict__ X, const float* __restrict__ W,
              const float* __restrict__ bias, float* __restrict__ out,
              int M, int N, int K) {
    __shared__ float Xs[128][20];   // [m][k], pad 20 -> conflict-free frags
    __shared__ float Ws[128][20];   // [n][k]

    const int tid  = threadIdx.x;
    const int lane = tid & 31;
    const int warp = tid >> 5;
    const int g = lane >> 2;     // groupID
    const int t = lane & 3;      // threadID in group
    const int wm = (warp >> 2) * 64;   // warp m offset (0/64)
    const int wn = (warp & 3) * 32;    // warp n offset (0/32/64/96)
    const int m0 = blockIdx.x * 128;
    const int n0 = blockIdx.y * 128;

    const int lr = tid >> 1;          // 0..127
    const int lc = (tid & 1) * 8;     // 0 or 8

    float c[4][4][4];
#pragma unroll
    for (int i = 0; i < 4; i++)
#pragma unroll
        for (int j = 0; j < 4; j++)
#pragma unroll
            for (int r = 0; r < 4; r++) c[i][j][r] = 0.f;

    for (int kt = 0; kt < K; kt += 16) {
        __syncthreads();
        // load + round X tile (128x16) and W tile (128x16)
        {
            const float* xp = &X[(size_t)(m0 + lr) * K + kt + lc];
            float4 v0 = *(const float4*)xp;
            float4 v1 = *(const float4*)(xp + 4);
            Xs[lr][lc + 0] = f2tf_f(v0.x); Xs[lr][lc + 1] = f2tf_f(v0.y);
            Xs[lr][lc + 2] = f2tf_f(v0.z); Xs[lr][lc + 3] = f2tf_f(v0.w);
            Xs[lr][lc + 4] = f2tf_f(v1.x); Xs[lr][lc + 5] = f2tf_f(v1.y);
            Xs[lr][lc + 6] = f2tf_f(v1.z); Xs[lr][lc + 7] = f2tf_f(v1.w);
            const float* wp = &W[(size_t)(n0 + lr) * K + kt + lc];
            float4 w0 = *(const float4*)wp;
            float4 w1 = *(const float4*)(wp + 4);
            Ws[lr][lc + 0] = f2tf_f(w0.x); Ws[lr][lc + 1] = f2tf_f(w0.y);
            Ws[lr][lc + 2] = f2tf_f(w0.z); Ws[lr][lc + 3] = f2tf_f(w0.w);
            Ws[lr][lc + 4] = f2tf_f(w1.x); Ws[lr][lc + 5] = f2tf_f(w1.y);
            Ws[lr][lc + 6] = f2tf_f(w1.z); Ws[lr][lc + 7] = f2tf_f(w1.w);
        }
        __syncthreads();

#pragma unroll
        for (int k8 = 0; k8 < 16; k8 += 8) {
            unsigned a[4][4], b[4][2];
#pragma unroll
            for (int mi = 0; mi < 4; mi++) {
                int rb = wm + mi * 16;
                a[mi][0] = __float_as_uint(Xs[rb + g][k8 + t]);
                a[mi][1] = __float_as_uint(Xs[rb + g + 8][k8 + t]);
                a[mi][2] = __float_as_uint(Xs[rb + g][k8 + t + 4]);
                a[mi][3] = __float_as_uint(Xs[rb + g + 8][k8 + t + 4]);
            }
#pragma unroll
            for (int nj = 0; nj < 4; nj++) {
                int nb = wn + nj * 8;
                b[nj][0] = __float_as_uint(Ws[nb + g][k8 + t]);
                b[nj][1] = __float_as_uint(Ws[nb + g][k8 + t + 4]);
            }
#pragma unroll
            for (int mi = 0; mi < 4; mi++)
#pragma unroll
                for (int nj = 0; nj < 4; nj++)
                    mma_tf32(c[mi][nj], a[mi][0], a[mi][1], a[mi][2], a[mi][3],
                             b[nj][0], b[nj][1]);
        }
    }

    // epilogue: bias + store
#pragma unroll
    for (int mi = 0; mi < 4; mi++) {
#pragma unroll
        for (int nj = 0; nj < 4; nj++) {
            int row = m0 + wm + mi * 16 + g;
            int col = n0 + wn + nj * 8 + 2 * t;
            float2 bv = *(const float2*)&bias[col];
            float2 r0, r1;
            r0.x = c[mi][nj][0] + bv.x;
            r0.y = c[mi][nj][1] + bv.y;
            r1.x = c[mi][nj][2] + bv.x;
            r1.y = c[mi][nj][3] + bv.y;
            *(float2*)&out[(size_t)row * N + col] = r0;
            *(float2*)&out[(size_t)(row + 8) * N + col] = r1;
        }
    }
}

// ============================================================================
// Flash attention with tf32 tensor cores.
// Grid (S/128, H, B), 256 threads = 8 warps; warp owns 16 query rows.
// Q kept in registers (a-frags) for whole kernel. K/V chunk = 64 keys.
// SMEM: Ks[64][72], Vs[64][72], Ps[128][68] (P staging + initial Q staging).
// ============================================================================
#define KST 72
#define PST 68
#define ATTN_SMEM_BYTES ((64 * KST + 64 * KST + 128 * PST) * 4)

__global__ __launch_bounds__(256, 2)
void attn_mma(const float* __restrict__ Qg, const float* __restrict__ Kg,
              const float* __restrict__ Vg, float* __restrict__ Og) {
    extern __shared__ float sm[];
    float* Ks = sm;                    // [64][72]
    float* Vs = Ks + 64 * KST;         // [64][72]
    float* Ps = Vs + 64 * KST;         // [128][68]

    const int b  = blockIdx.z;
    const int h  = blockIdx.y;
    const int q0 = blockIdx.x * 128;
    const int tid  = threadIdx.x;
    const int lane = tid & 31;
    const int warp = tid >> 5;
    const int g = lane >> 2;
    const int t = lane & 3;
    const int wq = warp * 16;          // warp's query-row offset in tile
    const float scale = 0.125f;        // 1/sqrt(64)

    // ---- stage Q tile into Ps (tf32-rounded, pre-scaled), then to registers
    {
        int r  = tid >> 1;
        int c0 = (tid & 1) * 32;
        const float* src = Qg + (size_t)(b * SS + q0 + r) * DD + h * DH + c0;
#pragma unroll
        for (int dd = 0; dd < 32; dd += 4) {
            float4 v = *(const float4*)(src + dd);
            Ps[r * PST + c0 + dd + 0] = f2tf_f(v.x * scale);
            Ps[r * PST + c0 + dd + 1] = f2tf_f(v.y * scale);
            Ps[r * PST + c0 + dd + 2] = f2tf_f(v.z * scale);
            Ps[r * PST + c0 + dd + 3] = f2tf_f(v.w * scale);
        }
    }
    __syncthreads();

    unsigned aq[8][4];
#pragma unroll
    for (int k8 = 0; k8 < 8; k8++) {
        aq[k8][0] = __float_as_uint(Ps[(wq + g) * PST + k8 * 8 + t]);
        aq[k8][1] = __float_as_uint(Ps[(wq + g + 8) * PST + k8 * 8 + t]);
        aq[k8][2] = __float_as_uint(Ps[(wq + g) * PST + k8 * 8 + t + 4]);
        aq[k8][3] = __float_as_uint(Ps[(wq + g + 8) * PST + k8 * 8 + t + 4]);
    }

    float o[8][4];
#pragma unroll
    for (int n = 0; n < 8; n++)
#pragma unroll
        for (int r = 0; r < 4; r++) o[n][r] = 0.f;
    float mrow[2] = {-1e30f, -1e30f};
    float lrow[2] = {0.f, 0.f};

    const int jl  = tid >> 2;          // 0..63 key row for loads
    const int dl0 = (tid & 3) * 16;    // d offset for loads
    const float* kb = Kg + (size_t)(b * SS) * DD + h * DH;
    const float* vb = Vg + (size_t)(b * SS) * DD + h * DH;

    for (int kt = 0; kt < SS; kt += 64) {
        __syncthreads();   // also protects Ps (Q staging / prev-iter P reads)
        // ---- load K/V chunk (tf32-rounded) ----
#pragma unroll
        for (int dd = 0; dd < 16; dd += 4) {
            float4 kv = *(const float4*)(kb + (size_t)(kt + jl) * DD + dl0 + dd);
            Ks[jl * KST + dl0 + dd + 0] = f2tf_f(kv.x);
            Ks[jl * KST + dl0 + dd + 1] = f2tf_f(kv.y);
            Ks[jl * KST + dl0 + dd + 2] = f2tf_f(kv.z);
            Ks[jl * KST + dl0 + dd + 3] = f2tf_f(kv.w);
            float4 vv = *(const float4*)(vb + (size_t)(kt + jl) * DD + dl0 + dd);
            Vs[jl * KST + dl0 + dd + 0] = f2tf_f(vv.x);
            Vs[jl * KST + dl0 + dd + 1] = f2tf_f(vv.y);
            Vs[jl * KST + dl0 + dd + 2] = f2tf_f(vv.z);
            Vs[jl * KST + dl0 + dd + 3] = f2tf_f(vv.w);
        }
        __syncthreads();

        // ---- S = Q @ K^T (warp tile 16 x 64) ----
        float s[8][4];
#pragma unroll
        for (int n = 0; n < 8; n++)
#pragma unroll
            for (int r = 0; r < 4; r++) s[n][r] = 0.f;
#pragma unroll
        for (int k8 = 0; k8 < 8; k8++) {
#pragma unroll
            for (int n = 0; n < 8; n++) {
                unsigned b0 = __float_as_uint(Ks[(n * 8 + g) * KST + k8 * 8 + t]);
                unsigned b1 = __float_as_uint(Ks[(n * 8 + g) * KST + k8 * 8 + t + 4]);
                mma_tf32(s[n], aq[k8][0], aq[k8][1], aq[k8][2], aq[k8][3], b0, b1);
            }
        }

        // ---- online softmax on fragment rows (g and g+8) ----
#pragma unroll
        for (int half = 0; half < 2; half++) {
            const int i0 = half * 2;
            float mx = -1e30f;
#pragma unroll
            for (int n = 0; n < 8; n++)
                mx = fmaxf(mx, fmaxf(s[n][i0], s[n][i0 + 1]));
            mx = fmaxf(mx, __shfl_xor_sync(0xffffffffu, mx, 1));
            mx = fmaxf(mx, __shfl_xor_sync(0xffffffffu, mx, 2));
            float mnew  = fmaxf(mrow[half], mx);
            float alpha = __expf(mrow[half] - mnew);
            float psum  = 0.f;
            int r = wq + g + half * 8;
#pragma unroll
            for (int n = 0; n < 8; n++) {
                float p0 = __expf(s[n][i0] - mnew);
                float p1 = __expf(s[n][i0 + 1] - mnew);
                psum += p0 + p1;
                float2 pw = make_float2(f2tf_f(p0), f2tf_f(p1));
                *(float2*)&Ps[r * PST + n * 8 + 2 * t] = pw;
            }
            psum += __shfl_xor_sync(0xffffffffu, psum, 1);
            psum += __shfl_xor_sync(0xffffffffu, psum, 2);
            lrow[half] = lrow[half] * alpha + psum;
            mrow[half] = mnew;
#pragma unroll
            for (int n = 0; n < 8; n++) {
                o[n][i0]     *= alpha;
                o[n][i0 + 1] *= alpha;
            }
        }
        __syncwarp();   // P rows are warp-private; order STS before LDS

        // ---- O += P @ V ----
#pragma unroll
        for (int k8 = 0; k8 < 8; k8++) {
            unsigned pa0 = __float_as_uint(Ps[(wq + g) * PST + k8 * 8 + t]);
            unsigned pa1 = __float_as_uint(Ps[(wq + g + 8) * PST + k8 * 8 + t]);
            unsigned pa2 = __float_as_uint(Ps[(wq + g) * PST + k8 * 8 + t + 4]);
            unsigned pa3 = __float_as_uint(Ps[(wq + g + 8) * PST + k8 * 8 + t + 4]);
#pragma unroll
            for (int n = 0; n < 8; n++) {
                unsigned b0 = __float_as_uint(Vs[(k8 * 8 + t) * KST + n * 8 + g]);
                unsigned b1 = __float_as_uint(Vs[(k8 * 8 + t + 4) * KST + n * 8 + g]);
                mma_tf32(o[n], pa0, pa1, pa2, pa3, b0, b1);
            }
        }
    }

    // ---- epilogue: normalize, write merged-head layout ----
    float inv0 = 1.f / lrow[0];
    float inv1 = 1.f / lrow[1];
#pragma unroll
    for (int n = 0; n < 8; n++) {
        int row = q0 + wq + g;
        int col = h * DH + n * 8 + 2 * t;
        float* dst0 = Og + (size_t)(b * SS + row) * DD + col;
        float* dst1 = Og + (size_t)(b * SS + row + 8) * DD + col;
        *(float2*)dst0 = make_float2(o[n][0] * inv0, o[n][1] * inv0);
        *(float2*)dst1 = make_float2(o[n][2] * inv1, o[n][3] * inv1);
    }
}

// ============================================================================
// kernel_launch
// ============================================================================
extern "C" void kernel_launch(void* const* d_in, const int* in_sizes, int n_in,
                              void* d_out, int out_size) {
    const float* q  = (const float*)d_in[0];
    const float* Wq = (const float*)d_in[1];
    const float* bq = (const float*)d_in[2];
    const float* Wk = (const float*)d_in[3];
    const float* bk = (const float*)d_in[4];
    const float* Wv = (const float*)d_in[5];
    const float* bv = (const float*)d_in[6];
    const float* Wo = (const float*)d_in[7];
    const float* bo = (const float*)d_in[8];
    float* out = (float*)d_out;

    float *gq, *gk, *gv, *ga;
    cudaGetSymbolAddress((void**)&gq, g_Q);
    cudaGetSymbolAddress((void**)&gk, g_K);
    cudaGetSymbolAddress((void**)&gv, g_V);
    cudaGetSymbolAddress((void**)&ga, g_A);

    cudaFuncSetAttribute(attn_mma, cudaFuncAttributeMaxDynamicSharedMemorySize,
                         ATTN_SMEM_BYTES);

    dim3 gemm_grid(TT / 128, DD / 128);  // (64, 4)
    dim3 gemm_block(256);

    gemm_mma<<<gemm_grid, gemm_block>>>(q, Wq, bq, gq, TT, DD, DD);
    gemm_mma<<<gemm_grid, gemm_block>>>(q, Wk, bk, gk, TT, DD, DD);
    gemm_mma<<<gemm_grid, gemm_block>>>(q, Wv, bv, gv, TT, DD, DD);

    dim3 attn_grid(SS / 128, HH, BB);    // (32, 8, 2)
    attn_mma<<<attn_grid, 256, ATTN_SMEM_BYTES>>>(gq, gk, gv, ga);

    gemm_mma<<<gemm_grid, gemm_block>>>(ga, Wo, bo, out, TT, DD, DD);
}

// round 5
// speedup vs baseline: 2.8854x; 1.2431x over previous
#include <cuda_runtime.h>
#include <cuda_bf16.h>
#include <math.h>
#include <stdint.h>

// Problem constants
#define BB 2
#define SS 4096
#define DD 512
#define HH 8
#define DH 64
#define TT (BB * SS)   // 8192 tokens

// ---------------- scratch (device globals; no allocations allowed) ----------
__device__ float g_Q[TT * DD];
__device__ float g_K[TT * DD];
__device__ float g_V[TT * DD];
__device__ float g_A[TT * DD];

// ---------------------------------------------------------------------------
// tf32 helpers (mma.sync m16n8k8 — sm_100 baseline ISA, no tcgen05)
// ---------------------------------------------------------------------------
__device__ __forceinline__ unsigned f2tf(float f) {
    unsigned u;
    asm("cvt.rna.tf32.f32 %0, %1;" : "=r"(u) : "f"(f));
    return u;
}
__device__ __forceinline__ float f2tf_f(float f) {
    return __uint_as_float(f2tf(f));
}
__device__ __forceinline__ void mma_tf32(float c[4],
                                         unsigned a0, unsigned a1,
                                         unsigned a2, unsigned a3,
                                         unsigned b0, unsigned b1) {
    asm volatile(
        "mma.sync.aligned.m16n8k8.row.col.f32.tf32.tf32.f32 "
        "{%0,%1,%2,%3}, {%4,%5,%6,%7}, {%8,%9}, {%0,%1,%2,%3};"
        : "+f"(c[0]), "+f"(c[1]), "+f"(c[2]), "+f"(c[3])
        : "r"(a0), "r"(a1), "r"(a2), "r"(a3), "r"(b0), "r"(b1));
}

// ============================================================================
// GEMM (unchanged from R2): out = X @ W^T + bias, tf32 mma.sync
// ============================================================================
__global__ __launch_bounds__(256, 2)
void gemm_mma(const float* __restrict__ X, const float* __restrict__ W,
              const float* __restrict__ bias, float* __restrict__ out,
              int M, int N, int K) {
    __shared__ float Xs[128][20];
    __shared__ float Ws[128][20];

    const int tid  = threadIdx.x;
    const int lane = tid & 31;
    const int warp = tid >> 5;
    const int g = lane >> 2;
    const int t = lane & 3;
    const int wm = (warp >> 2) * 64;
    const int wn = (warp & 3) * 32;
    const int m0 = blockIdx.x * 128;
    const int n0 = blockIdx.y * 128;

    const int lr = tid >> 1;
    const int lc = (tid & 1) * 8;

    float c[4][4][4];
#pragma unroll
    for (int i = 0; i < 4; i++)
#pragma unroll
        for (int j = 0; j < 4; j++)
#pragma unroll
            for (int r = 0; r < 4; r++) c[i][j][r] = 0.f;

    for (int kt = 0; kt < K; kt += 16) {
        __syncthreads();
        {
            const float* xp = &X[(size_t)(m0 + lr) * K + kt + lc];
            float4 v0 = *(const float4*)xp;
            float4 v1 = *(const float4*)(xp + 4);
            Xs[lr][lc + 0] = f2tf_f(v0.x); Xs[lr][lc + 1] = f2tf_f(v0.y);
            Xs[lr][lc + 2] = f2tf_f(v0.z); Xs[lr][lc + 3] = f2tf_f(v0.w);
            Xs[lr][lc + 4] = f2tf_f(v1.x); Xs[lr][lc + 5] = f2tf_f(v1.y);
            Xs[lr][lc + 6] = f2tf_f(v1.z); Xs[lr][lc + 7] = f2tf_f(v1.w);
            const float* wp = &W[(size_t)(n0 + lr) * K + kt + lc];
            float4 w0 = *(const float4*)wp;
            float4 w1 = *(const float4*)(wp + 4);
            Ws[lr][lc + 0] = f2tf_f(w0.x); Ws[lr][lc + 1] = f2tf_f(w0.y);
            Ws[lr][lc + 2] = f2tf_f(w0.z); Ws[lr][lc + 3] = f2tf_f(w0.w);
            Ws[lr][lc + 4] = f2tf_f(w1.x); Ws[lr][lc + 5] = f2tf_f(w1.y);
            Ws[lr][lc + 6] = f2tf_f(w1.z); Ws[lr][lc + 7] = f2tf_f(w1.w);
        }
        __syncthreads();

#pragma unroll
        for (int k8 = 0; k8 < 16; k8 += 8) {
            unsigned a[4][4], b[4][2];
#pragma unroll
            for (int mi = 0; mi < 4; mi++) {
                int rb = wm + mi * 16;
                a[mi][0] = __float_as_uint(Xs[rb + g][k8 + t]);
                a[mi][1] = __float_as_uint(Xs[rb + g + 8][k8 + t]);
                a[mi][2] = __float_as_uint(Xs[rb + g][k8 + t + 4]);
                a[mi][3] = __float_as_uint(Xs[rb + g + 8][k8 + t + 4]);
            }
#pragma unroll
            for (int nj = 0; nj < 4; nj++) {
                int nb = wn + nj * 8;
                b[nj][0] = __float_as_uint(Ws[nb + g][k8 + t]);
                b[nj][1] = __float_as_uint(Ws[nb + g][k8 + t + 4]);
            }
#pragma unroll
            for (int mi = 0; mi < 4; mi++)
#pragma unroll
                for (int nj = 0; nj < 4; nj++)
                    mma_tf32(c[mi][nj], a[mi][0], a[mi][1], a[mi][2], a[mi][3],
                             b[nj][0], b[nj][1]);
        }
    }

#pragma unroll
    for (int mi = 0; mi < 4; mi++) {
#pragma unroll
        for (int nj = 0; nj < 4; nj++) {
            int row = m0 + wm + mi * 16 + g;
            int col = n0 + wn + nj * 8 + 2 * t;
            float2 bv = *(const float2*)&bias[col];
            float2 r0, r1;
            r0.x = c[mi][nj][0] + bv.x;
            r0.y = c[mi][nj][1] + bv.y;
            r1.x = c[mi][nj][2] + bv.x;
            r1.y = c[mi][nj][3] + bv.y;
            *(float2*)&out[(size_t)row * N + col] = r0;
            *(float2*)&out[(size_t)(row + 8) * N + col] = r1;
        }
    }
}

// ============================================================================
// Flash attention, tf32 mma.sync, warp_M = 32 (halves per-work K/V LDS reads).
// Grid (S/256, H, B), 256 threads = 8 warps; warp owns 32 query rows.
// Q fragments live in registers for the whole kernel.
// SMEM: Ks[64][72], Vs[64][72], Ps[256][68] (P staging + initial Q staging).
// ============================================================================
#define KST 72
#define PST 68
#define QTILE 256
#define ATTN_SMEM_BYTES ((64 * KST + 64 * KST + QTILE * PST) * 4)

__global__ __launch_bounds__(256, 1)
void attn_mma(const float* __restrict__ Qg, const float* __restrict__ Kg,
              const float* __restrict__ Vg, float* __restrict__ Og) {
    extern __shared__ float sm[];
    float* Ks = sm;                    // [64][72]
    float* Vs = Ks + 64 * KST;         // [64][72]
    float* Ps = Vs + 64 * KST;         // [256][68]

    const int b  = blockIdx.z;
    const int h  = blockIdx.y;
    const int q0 = blockIdx.x * QTILE;
    const int tid  = threadIdx.x;
    const int lane = tid & 31;
    const int warp = tid >> 5;
    const int g = lane >> 2;
    const int t = lane & 3;
    const int wq = warp * 32;          // warp's query-row offset in tile
    const float scale = 0.125f;        // 1/sqrt(64)

    // ---- stage Q tile into Ps (tf32-rounded, pre-scaled) ----
    {
        int r = tid;                   // one row per thread
        const float* src = Qg + (size_t)(b * SS + q0 + r) * DD + h * DH;
#pragma unroll
        for (int dd = 0; dd < 64; dd += 4) {
            float4 v = *(const float4*)(src + dd);
            Ps[r * PST + dd + 0] = f2tf_f(v.x * scale);
            Ps[r * PST + dd + 1] = f2tf_f(v.y * scale);
            Ps[r * PST + dd + 2] = f2tf_f(v.z * scale);
            Ps[r * PST + dd + 3] = f2tf_f(v.w * scale);
        }
    }
    __syncthreads();

    // ---- Q fragments to registers: aq[k8][mi][4]  (mi = m-tile 0/1) ----
    unsigned aq[8][2][4];
#pragma unroll
    for (int k8 = 0; k8 < 8; k8++) {
#pragma unroll
        for (int mi = 0; mi < 2; mi++) {
            int rb = wq + mi * 16;
            aq[k8][mi][0] = __float_as_uint(Ps[(rb + g) * PST + k8 * 8 + t]);
            aq[k8][mi][1] = __float_as_uint(Ps[(rb + g + 8) * PST + k8 * 8 + t]);
            aq[k8][mi][2] = __float_as_uint(Ps[(rb + g) * PST + k8 * 8 + t + 4]);
            aq[k8][mi][3] = __float_as_uint(Ps[(rb + g + 8) * PST + k8 * 8 + t + 4]);
        }
    }

    float o[2][8][4];
#pragma unroll
    for (int mi = 0; mi < 2; mi++)
#pragma unroll
        for (int n = 0; n < 8; n++)
#pragma unroll
            for (int r = 0; r < 4; r++) o[mi][n][r] = 0.f;
    float mrow[2][2] = {{-1e30f, -1e30f}, {-1e30f, -1e30f}};
    float lrow[2][2] = {{0.f, 0.f}, {0.f, 0.f}};

    const int jl  = tid >> 2;          // 0..63 key row for loads
    const int dl0 = (tid & 3) * 16;    // d offset for loads
    const float* kb = Kg + (size_t)(b * SS) * DD + h * DH;
    const float* vb = Vg + (size_t)(b * SS) * DD + h * DH;

    for (int kt = 0; kt < SS; kt += 64) {
        __syncthreads();   // prev-iter K/V/P consumers done
        // ---- load K/V chunk (tf32-rounded) ----
#pragma unroll
        for (int dd = 0; dd < 16; dd += 4) {
            float4 kv = *(const float4*)(kb + (size_t)(kt + jl) * DD + dl0 + dd);
            Ks[jl * KST + dl0 + dd + 0] = f2tf_f(kv.x);
            Ks[jl * KST + dl0 + dd + 1] = f2tf_f(kv.y);
            Ks[jl * KST + dl0 + dd + 2] = f2tf_f(kv.z);
            Ks[jl * KST + dl0 + dd + 3] = f2tf_f(kv.w);
            float4 vv = *(const float4*)(vb + (size_t)(kt + jl) * DD + dl0 + dd);
            Vs[jl * KST + dl0 + dd + 0] = f2tf_f(vv.x);
            Vs[jl * KST + dl0 + dd + 1] = f2tf_f(vv.y);
            Vs[jl * KST + dl0 + dd + 2] = f2tf_f(vv.z);
            Vs[jl * KST + dl0 + dd + 3] = f2tf_f(vv.w);
        }
        __syncthreads();

        // ---- S = Q @ K^T (warp tile 32 x 64) ----
        float s[2][8][4];
#pragma unroll
        for (int mi = 0; mi < 2; mi++)
#pragma unroll
            for (int n = 0; n < 8; n++)
#pragma unroll
                for (int r = 0; r < 4; r++) s[mi][n][r] = 0.f;
#pragma unroll
        for (int k8 = 0; k8 < 8; k8++) {
#pragma unroll
            for (int n = 0; n < 8; n++) {
                unsigned b0 = __float_as_uint(Ks[(n * 8 + g) * KST + k8 * 8 + t]);
                unsigned b1 = __float_as_uint(Ks[(n * 8 + g) * KST + k8 * 8 + t + 4]);
#pragma unroll
                for (int mi = 0; mi < 2; mi++)
                    mma_tf32(s[mi][n], aq[k8][mi][0], aq[k8][mi][1],
                             aq[k8][mi][2], aq[k8][mi][3], b0, b1);
            }
        }

        // ---- online softmax on fragment rows, stage P to SMEM ----
#pragma unroll
        for (int mi = 0; mi < 2; mi++) {
#pragma unroll
            for (int half = 0; half < 2; half++) {
                const int i0 = half * 2;
                float mx = -1e30f;
#pragma unroll
                for (int n = 0; n < 8; n++)
                    mx = fmaxf(mx, fmaxf(s[mi][n][i0], s[mi][n][i0 + 1]));
                mx = fmaxf(mx, __shfl_xor_sync(0xffffffffu, mx, 1));
                mx = fmaxf(mx, __shfl_xor_sync(0xffffffffu, mx, 2));
                float mnew  = fmaxf(mrow[mi][half], mx);
                float alpha = __expf(mrow[mi][half] - mnew);
                float psum  = 0.f;
                int r = wq + mi * 16 + g + half * 8;
#pragma unroll
                for (int n = 0; n < 8; n++) {
                    float p0 = __expf(s[mi][n][i0] - mnew);
                    float p1 = __expf(s[mi][n][i0 + 1] - mnew);
                    psum += p0 + p1;
                    *(float2*)&Ps[r * PST + n * 8 + 2 * t] =
                        make_float2(f2tf_f(p0), f2tf_f(p1));
                }
                psum += __shfl_xor_sync(0xffffffffu, psum, 1);
                psum += __shfl_xor_sync(0xffffffffu, psum, 2);
                lrow[mi][half] = lrow[mi][half] * alpha + psum;
                mrow[mi][half] = mnew;
#pragma unroll
                for (int n = 0; n < 8; n++) {
                    o[mi][n][i0]     *= alpha;
                    o[mi][n][i0 + 1] *= alpha;
                }
            }
        }
        __syncwarp();   // P rows are warp-private; order STS before LDS

        // ---- O += P @ V ----
#pragma unroll
        for (int k8 = 0; k8 < 8; k8++) {
            unsigned pa[2][4];
#pragma unroll
            for (int mi = 0; mi < 2; mi++) {
                int rb = wq + mi * 16;
                pa[mi][0] = __float_as_uint(Ps[(rb + g) * PST + k8 * 8 + t]);
                pa[mi][1] = __float_as_uint(Ps[(rb + g + 8) * PST + k8 * 8 + t]);
                pa[mi][2] = __float_as_uint(Ps[(rb + g) * PST + k8 * 8 + t + 4]);
                pa[mi][3] = __float_as_uint(Ps[(rb + g + 8) * PST + k8 * 8 + t + 4]);
            }
#pragma unroll
            for (int n = 0; n < 8; n++) {
                unsigned b0 = __float_as_uint(Vs[(k8 * 8 + t) * KST + n * 8 + g]);
                unsigned b1 = __float_as_uint(Vs[(k8 * 8 + t + 4) * KST + n * 8 + g]);
#pragma unroll
                for (int mi = 0; mi < 2; mi++)
                    mma_tf32(o[mi][n], pa[mi][0], pa[mi][1], pa[mi][2], pa[mi][3],
                             b0, b1);
            }
        }
    }

    // ---- epilogue: normalize, write merged-head layout ----
#pragma unroll
    for (int mi = 0; mi < 2; mi++) {
        float inv0 = 1.f / lrow[mi][0];
        float inv1 = 1.f / lrow[mi][1];
#pragma unroll
        for (int n = 0; n < 8; n++) {
            int row = q0 + wq + mi * 16 + g;
            int col = h * DH + n * 8 + 2 * t;
            float* dst0 = Og + (size_t)(b * SS + row) * DD + col;
            float* dst1 = Og + (size_t)(b * SS + row + 8) * DD + col;
            *(float2*)dst0 = make_float2(o[mi][n][0] * inv0, o[mi][n][1] * inv0);
            *(float2*)dst1 = make_float2(o[mi][n][2] * inv1, o[mi][n][3] * inv1);
        }
    }
}

// ============================================================================
// kernel_launch
// ============================================================================
extern "C" void kernel_launch(void* const* d_in, const int* in_sizes, int n_in,
                              void* d_out, int out_size) {
    const float* q  = (const float*)d_in[0];
    const float* Wq = (const float*)d_in[1];
    const float* bq = (const float*)d_in[2];
    const float* Wk = (const float*)d_in[3];
    const float* bk = (const float*)d_in[4];
    const float* Wv = (const float*)d_in[5];
    const float* bv = (const float*)d_in[6];
    const float* Wo = (const float*)d_in[7];
    const float* bo = (const float*)d_in[8];
    float* out = (float*)d_out;

    float *gq, *gk, *gv, *ga;
    cudaGetSymbolAddress((void**)&gq, g_Q);
    cudaGetSymbolAddress((void**)&gk, g_K);
    cudaGetSymbolAddress((void**)&gv, g_V);
    cudaGetSymbolAddress((void**)&ga, g_A);

    cudaFuncSetAttribute(attn_mma, cudaFuncAttributeMaxDynamicSharedMemorySize,
                         ATTN_SMEM_BYTES);

    dim3 gemm_grid(TT / 128, DD / 128);  // (64, 4)
    dim3 gemm_block(256);

    gemm_mma<<<gemm_grid, gemm_block>>>(q, Wq, bq, gq, TT, DD, DD);
    gemm_mma<<<gemm_grid, gemm_block>>>(q, Wk, bk, gk, TT, DD, DD);
    gemm_mma<<<gemm_grid, gemm_block>>>(q, Wv, bv, gv, TT, DD, DD);

    dim3 attn_grid(SS / QTILE, HH, BB);  // (16, 8, 2)
    attn_mma<<<attn_grid, 256, ATTN_SMEM_BYTES>>>(gq, gk, gv, ga);

    gemm_mma<<<gemm_grid, gemm_block>>>(ga, Wo, bo, out, TT, DD, DD);
}